// round 1
// baseline (speedup 1.0000x reference)
#include <cuda_runtime.h>
#include <math.h>

#define NPTS     72
#define NSTRIPSF 71.0f
#define NLANE    4
#define NP       192
#define STAGES   3
#define BATCH    512
#define DD       78
#define PITCH    79
#define NBLK     (STAGES*BATCH)
#define IMGW     800.0f
#define IMGH     320.0f

// Per-block partial results (deterministic two-pass reduction, no atomics).
__device__ float g_partials[NBLK];

__device__ __forceinline__ float warpRedSum(float v){
#pragma unroll
    for (int o = 16; o; o >>= 1) v += __shfl_down_sync(0xffffffffu, v, o);
    return v;
}
__device__ __forceinline__ float warpRedMax(float v){
#pragma unroll
    for (int o = 16; o; o >>= 1) v = fmaxf(v, __shfl_down_sync(0xffffffffu, v, o));
    return v;
}

// 192-thread (6-warp) block reductions. red must have >= 8 floats.
__device__ float blkSum(float v, float* red, int tid){
    v = warpRedSum(v);
    if ((tid & 31) == 0) red[tid >> 5] = v;
    __syncthreads();
    if (tid == 0){ float s = red[0]; for (int w = 1; w < 6; w++) s += red[w]; red[6] = s; }
    __syncthreads();
    float r = red[6];
    __syncthreads();
    return r;
}
__device__ float blkMax(float v, float* red, int tid){
    v = warpRedMax(v);
    if ((tid & 31) == 0) red[tid >> 5] = v;
    __syncthreads();
    if (tid == 0){ float s = red[0]; for (int w = 1; w < 6; w++) s = fmaxf(s, red[w]); red[6] = s; }
    __syncthreads();
    float r = red[6];
    __syncthreads();
    return r;
}

__device__ __forceinline__ float smooth_l1(float x){
    float a = fabsf(x);
    return (a < 1.0f) ? 0.5f * x * x : a - 0.5f;
}

__global__ void __launch_bounds__(192, 1)
clr_main(const float* __restrict__ predA, const float* __restrict__ tgtA)
{
    extern __shared__ float sm[];
    float* P     = sm;                      // [NP][PITCH]
    float* T     = P + NP * PITCH;          // [NLANE][DD]
    float* sIou  = T + NLANE * DD;          // [NLANE][NP] lane-major
    float* sCost = sIou + NLANE * NP;       // [NLANE][NP] lane-major
    float* red   = sCost + NLANE * NP;      // [8]
    float* laneF = red + 8;                 // [8]: tlen[0..3], valid[4..7]
    int*   dynk  = (int*)(laneF + 8);       // [4]

    const int tid = threadIdx.x;
    const int blk = blockIdx.x;             // s*BATCH + b
    const int b   = blk & (BATCH - 1);
    const float* pred = predA + (size_t)blk * (NP * DD);
    const float* tgt  = tgtA  + (size_t)b   * (NLANE * DD);

    // ---- stage tiles into shared (coalesced) ----
    for (int idx = tid; idx < NP * DD; idx += 192){
        int r = idx / DD; int c = idx - r * DD;
        P[r * PITCH + c] = pred[idx];
    }
    for (int idx = tid; idx < NLANE * DD; idx += 192) T[idx] = tgt[idx];
    __syncthreads();

    // ---- lane scalars ----
    if (tid < NLANE){
        const float* t = T + tid * DD;
        float tl = 0.0f;
        for (int j = 0; j < NPTS; j++){
            float x = t[6 + j];
            if (x >= 0.0f && x < IMGW) tl += 1.0f;
        }
        laneF[tid]     = tl;
        laneF[4 + tid] = (t[1] == 1.0f) ? 1.0f : 0.0f;
    }
    __syncthreads();

    // ---- per-prior point loop: iou numer/denom, dist sum ----
    const float* p = P + tid * PITCH;
    const float p0 = p[0], p1 = p[1], p2 = p[2], p3 = p[3], p4 = p[4], p5 = p[5];

    float ovr[NLANE] = {0,0,0,0}, uni[NLANE] = {0,0,0,0}, dsum[NLANE] = {0,0,0,0};
    for (int j = 0; j < NPTS; j++){
        float px  = p[6 + j] * (IMGW - 1.0f);
        float pxl = px - 15.0f, pxh = px + 15.0f;
#pragma unroll
        for (int l = 0; l < NLANE; l++){
            float tx = T[l * DD + 6 + j];
            if (tx >= 0.0f && tx < IMGW){
                ovr[l]  += fminf(pxh, tx + 15.0f) - fmaxf(pxl, tx - 15.0f);
                uni[l]  += fmaxf(pxh, tx + 15.0f) - fminf(pxl, tx - 15.0f);
                dsum[l] += fabsf(tx - px);
            }
        }
    }

    float myIou[NLANE], myDist[NLANE], mySd[NLANE], myTh[NLANE], vL[NLANE];
    float lmD = -INFINITY, lmS = -INFINITY, lmT = -INFINITY;
#pragma unroll
    for (int l = 0; l < NLANE; l++){
        float iou  = ovr[l] / (uni[l] + 1e-9f);
        myIou[l]   = iou;
        sIou[l * NP + tid] = iou;
        float dist = dsum[l] / (laneF[l] + 1e-9f);
        myDist[l]  = dist;
        float dy = p2 * (IMGH - 1.0f) - T[l * DD + 2] * (IMGH - 1.0f);
        float dx = p3 * (IMGW - 1.0f) - T[l * DD + 3];
        float sd = sqrtf(dy * dy + dx * dx);
        mySd[l] = sd;
        float th = fabsf(p4 - T[l * DD + 4]) * 180.0f;
        myTh[l] = th;
        float v = laneF[4 + l];
        vL[l] = v;
        if (v > 0.0f){
            lmD = fmaxf(lmD, dist);
            lmS = fmaxf(lmS, sd);
            lmT = fmaxf(lmT, th);
        }
    }

    const float num_t = laneF[4] + laneF[5] + laneF[6] + laneF[7];
    const bool  has_t = num_t > 0.0f;

    float mD = blkMax(lmD, red, tid);
    float mS = blkMax(lmS, red, tid);
    float mT = blkMax(lmT, red, tid);
    if (!has_t){ mD = 1.0f; mS = 1.0f; mT = 1.0f; }

    // ---- classification cost (component 1 only) ----
    float sp1  = 1.0f / (1.0f + expf(-p1));
    float neg1 = -logf(1.0f - sp1 + 1e-12f) * 0.75f * sp1 * sp1;
    float pos1 = -logf(sp1 + 1e-12f) * 0.25f * (1.0f - sp1) * (1.0f - sp1);
    float clsc = pos1 - neg1;

    // ---- cost matrix ----
    float costr[NLANE];
#pragma unroll
    for (int l = 0; l < NLANE; l++){
        float ds = 1.0f - myDist[l] / mD + 0.01f;
        float ss = 1.0f - mySd[l]  / mS + 0.01f;
        float ts = 1.0f - myTh[l]  / mT + 0.01f;
        float prod = ds * ss * ts;
        float c = -(prod * prod) * 3.0f + clsc;
        c = (vL[l] > 0.0f) ? c : INFINITY;
        costr[l] = c;
        sCost[l * NP + tid] = c;
    }
    int amin = 0;
    {
        float bc = costr[0];
#pragma unroll
        for (int l = 1; l < NLANE; l++){ if (costr[l] < bc){ bc = costr[l]; amin = l; } }
    }
    __syncthreads();

    // ---- dyn_k per lane: top-4 of iou_sg over priors ----
    if (tid < NLANE){
        float t0 = 0.f, t1 = 0.f, t2v = 0.f, t3v = 0.f;
        float v = laneF[4 + tid];
        const float* srow = sIou + tid * NP;
        for (int k = 0; k < NP; k++){
            float x = (v > 0.0f) ? fmaxf(srow[k], 0.0f) : 0.0f;
            if      (x > t0){ t3v = t2v; t2v = t1; t1 = t0; t0 = x; }
            else if (x > t1){ t3v = t2v; t2v = t1; t1 = x; }
            else if (x > t2v){ t3v = t2v; t2v = x; }
            else if (x > t3v){ t3v = x; }
        }
        float s = t0 + t1 + t2v + t3v;
        int dk = (int)s;                 // trunc toward zero == floor (s >= 0)
        if (dk < 1) dk = 1;
        dynk[tid] = dk;
    }
    __syncthreads();

    // ---- ranks via stable count (== double-argsort), matching matrix M ----
    float Mf[NLANE];
    int nM = 0;
#pragma unroll
    for (int l = 0; l < NLANE; l++){
        float m = 0.0f;
        if (vL[l] > 0.0f){
            float ci = costr[l];
            const float* crow = sCost + l * NP;
            int cnt = 0;
            for (int k = 0; k < NP; k++){
                float ck = crow[k];
                cnt += (ck < ci) ? 1 : ((ck == ci && k < tid) ? 1 : 0);
            }
            if (cnt < dynk[l]){ m = 1.0f; nM++; }
        }
        Mf[l] = m;
    }
    if (nM > 1){ Mf[0] = 0.0f; Mf[amin] = 1.0f; }   // reference's multi-match fixup

    float mfsum = Mf[0] + Mf[1] + Mf[2] + Mf[3];
    int clsT = (mfsum > 0.0f) ? 1 : 0;

    // ---- focal term ----
    float mxl = fmaxf(p0, p1);
    float e0 = expf(p0 - mxl), e1 = expf(p1 - mxl);
    float pt = ((clsT ? e1 : e0) / (e0 + e1)) + 1e-8f;
    float focal = -0.25f * (1.0f - pt) * (1.0f - pt) * logf(pt);

    // ---- reg + iou terms ----
    float yv = p2 * NSTRIPSF, xv = p3 * (IMGW - 1.0f), tv = p4 * 180.0f, lv = p5 * NSTRIPSF;
    float pstart = fminf(fmaxf(rintf(p2 * NSTRIPSF), 0.0f), NSTRIPSF);
    float regp = 0.0f, ioup = 0.0f;
#pragma unroll
    for (int l = 0; l < NLANE; l++){
        if (Mf[l] > 0.0f){
            const float* t = T + l * DD;
            float d1 = yv - t[2] * NSTRIPSF;
            float d2 = xv - t[3];
            float d3 = tv - t[4] * 180.0f;
            float tstart = rintf(t[2] * NSTRIPSF);
            float tlp = t[5] - (pstart - tstart);
            float d4 = lv - tlp;
            regp += smooth_l1(d1) + smooth_l1(d2) + smooth_l1(d3) + smooth_l1(d4);
            ioup += 1.0f - myIou[l];
        }
    }

    float nmatch  = blkSum(mfsum, red, tid);
    float focal_s = blkSum(focal, red, tid);
    float reg_s   = blkSum(regp,  red, tid);
    float iou_s   = blkSum(ioup,  red, tid);

    if (tid == 0){
        float cls_term = focal_s / (has_t ? num_t : 1.0f);
        float reg_term = has_t ? reg_s / fmaxf(nmatch * 4.0f, 1.0f) : 0.0f;
        float iou_term = has_t ? iou_s / fmaxf(nmatch, 1.0f) : 0.0f;
        g_partials[blk] = 2.0f * cls_term + 0.2f * reg_term + 2.0f * iou_term;
    }
}

__global__ void clr_reduce(const float* __restrict__ seg, float* __restrict__ out)
{
    __shared__ float s[512];
    int tid = threadIdx.x;
    float v = 0.0f;
    for (int i = tid; i < NBLK; i += 512) v += g_partials[i];
    s[tid] = v;
    __syncthreads();
    for (int o = 256; o; o >>= 1){
        if (tid < o) s[tid] += s[tid + o];
        __syncthreads();
    }
    if (tid == 0) out[0] = s[0] / (float)NBLK + seg[0];
}

extern "C" void kernel_launch(void* const* d_in, const int* in_sizes, int n_in,
                              void* d_out, int out_size)
{
    const float* pred = (const float*)d_in[0];
    const float* tgt  = (const float*)d_in[1];
    const float* seg  = (const float*)d_in[2];
    float* out = (float*)d_out;

    const size_t smem = (size_t)(NP * PITCH + NLANE * DD + 2 * NLANE * NP + 8 + 8) * sizeof(float)
                      + 4 * sizeof(int);
    cudaFuncSetAttribute(clr_main, cudaFuncAttributeMaxDynamicSharedMemorySize, (int)smem);

    clr_main<<<NBLK, 192, smem>>>(pred, tgt);
    clr_reduce<<<1, 512>>>(seg, out);
}

// round 2
// speedup vs baseline: 2.1628x; 2.1628x over previous
#include <cuda_runtime.h>
#include <math.h>

#define NPTS     72
#define NSTRIPSF 71.0f
#define NLANE    4
#define NP       192
#define BATCH    512
#define DD       78
#define NBLK     1536
#define IMGW     800.0f
#define IMGH     320.0f
#define XPITCH   73
#define SPITCH   7

__device__ float g_partials[NBLK];

__device__ __forceinline__ unsigned umn(unsigned a, unsigned b){ return a < b ? a : b; }
__device__ __forceinline__ unsigned umx(unsigned a, unsigned b){ return a > b ? a : b; }

// monotonic float -> uint map (ascending uint order == ascending float order)
__device__ __forceinline__ unsigned fkey(float f){
    int b = __float_as_int(f);
    return (b >= 0) ? ((unsigned)b ^ 0x80000000u) : ~((unsigned)b);
}
__device__ __forceinline__ float smooth_l1(float x){
    float a = fabsf(x);
    return (a < 1.0f) ? 0.5f * x * x : a - 0.5f;
}

struct __align__(16) SMLayout {
    float    xs[NP * XPITCH];     // pred xs premultiplied by (IMGW-1)
    float    scal[NP * SPITCH];   // p0..p5 per prior
    float4   tp[NLANE * NPTS];    // compacted (tx-15, tx+15, tx, j_bits)
    unsigned key[NLANE * NP];     // cost order-keys, lane-major
    float    iouc[NLANE * NP];    // clamped iou (iou_sg), lane-major
    float    laneA[NLANE * 8];    // [0]=valid [1]=tlen [2..5]=t2..t5
    int      cnt[NLANE];
    unsigned thr[NLANE];          // dyn_k-th smallest cost key per lane
    float    red[32];
};

__global__ void __launch_bounds__(192)
clr_main(const float* __restrict__ predA, const float* __restrict__ tgtA)
{
    extern __shared__ char smraw[];
    SMLayout& s = *reinterpret_cast<SMLayout*>(smraw);

    const int tid  = threadIdx.x;
    const int wid  = tid >> 5;
    const int lane = tid & 31;
    const int blk  = blockIdx.x;
    const int b    = blk & (BATCH - 1);

    const float2* pred2 = (const float2*)(predA + (size_t)blk * (NP * DD));
    const float*  tgt   = tgtA + (size_t)b * (NLANE * DD);

    // ---- stage predictions (coalesced float2), split scalars / xs(premul) ----
#pragma unroll 4
    for (int k = 0; k < 39; k++){
        int idx = tid + k * 192;            // 39*192 = 7488 float2 = 192*78 floats
        int r = idx / 39, c2 = idx - r * 39;
        float2 v = pred2[idx];
        if (c2 < 3){
            s.scal[r * SPITCH + 2 * c2]     = v.x;
            s.scal[r * SPITCH + 2 * c2 + 1] = v.y;
        } else {
            int c = 2 * c2 - 6;
            s.xs[r * XPITCH + c]     = v.x * (IMGW - 1.0f);
            s.xs[r * XPITCH + c + 1] = v.y * (IMGW - 1.0f);
        }
    }

    // ---- compact targets per lane (warps 0..3), keep ascending j ----
    if (wid < NLANE){
        const float* t = tgt + wid * DD;
        int base = 0;
#pragma unroll
        for (int c = 0; c < 3; c++){
            int j = c * 32 + lane;
            float x = (j < NPTS) ? t[6 + j] : -1.0f;
            bool ok = (x >= 0.0f) && (x < IMGW);
            unsigned m = __ballot_sync(0xffffffffu, ok);
            if (ok){
                int pos = base + __popc(m & ((1u << lane) - 1u));
                s.tp[wid * NPTS + pos] = make_float4(x - 15.0f, x + 15.0f, x, __int_as_float(j));
            }
            base += __popc(m);
        }
        if (lane == 0){
            s.cnt[wid] = base;
            float* la = s.laneA + wid * 8;
            la[0] = (t[1] == 1.0f) ? 1.0f : 0.0f;
            la[1] = (float)base;                 // t_len == #valid points
            la[2] = t[2]; la[3] = t[3]; la[4] = t[4]; la[5] = t[5];
        }
    }
    __syncthreads();

    // ---- per-prior point loop over compacted valid points ----
    const float* myxs = s.xs + tid * XPITCH;
    float myIou[NLANE], myDist[NLANE];
#pragma unroll
    for (int l = 0; l < NLANE; l++){
        const int nv = s.cnt[l];
        const float4* tpl = s.tp + l * NPTS;
        float o = 0.0f, u = 0.0f, d = 0.0f;
#pragma unroll 2
        for (int n = 0; n < nv; n++){
            float4 e = tpl[n];                       // broadcast LDS.128
            float px = myxs[__float_as_int(e.w)];    // conflict-free (pitch 73)
            float pl = px - 15.0f, ph = px + 15.0f;
            o += fminf(ph, e.y) - fmaxf(pl, e.x);
            u += fmaxf(ph, e.y) - fminf(pl, e.x);
            d += fabsf(e.z - px);
        }
        myIou[l]  = o / (u + 1e-9f);
        myDist[l] = d / (s.laneA[l * 8 + 1] + 1e-9f);
    }

    // ---- per-lane geometric scores + local maxima ----
    const float* ps = s.scal + tid * SPITCH;
    const float p0 = ps[0], p1 = ps[1], p2 = ps[2], p3 = ps[3], p4 = ps[4], p5 = ps[5];
    float vL[NLANE], mySd[NLANE], myTh[NLANE];
    float lmD = -INFINITY, lmS = -INFINITY, lmT = -INFINITY;
    const float py = p2 * (IMGH - 1.0f), pxc = p3 * (IMGW - 1.0f);
#pragma unroll
    for (int l = 0; l < NLANE; l++){
        const float* la = s.laneA + l * 8;
        float v = la[0]; vL[l] = v;
        float dy = py - la[2] * (IMGH - 1.0f);
        float dx = pxc - la[3];
        float sd = sqrtf(dy * dy + dx * dx);
        mySd[l] = sd;
        float th = fabsf(p4 - la[4]) * 180.0f;
        myTh[l] = th;
        if (v > 0.0f){
            lmD = fmaxf(lmD, myDist[l]);
            lmS = fmaxf(lmS, sd);
            lmT = fmaxf(lmT, th);
        }
    }
    const float num_t = vL[0] + vL[1] + vL[2] + vL[3];
    const bool  has_t = num_t > 0.0f;

    // ---- fused 3-way block max ----
#pragma unroll
    for (int o2 = 16; o2; o2 >>= 1){
        lmD = fmaxf(lmD, __shfl_xor_sync(0xffffffffu, lmD, o2));
        lmS = fmaxf(lmS, __shfl_xor_sync(0xffffffffu, lmS, o2));
        lmT = fmaxf(lmT, __shfl_xor_sync(0xffffffffu, lmT, o2));
    }
    if (lane == 0){ s.red[wid] = lmD; s.red[8 + wid] = lmS; s.red[16 + wid] = lmT; }
    __syncthreads();
    float mD = s.red[0], mS = s.red[8], mT = s.red[16];
#pragma unroll
    for (int w = 1; w < 6; w++){
        mD = fmaxf(mD, s.red[w]);
        mS = fmaxf(mS, s.red[8 + w]);
        mT = fmaxf(mT, s.red[16 + w]);
    }
    if (!has_t){ mD = 1.0f; mS = 1.0f; mT = 1.0f; }

    // ---- classification cost + cost matrix (as order keys) ----
    float sp1  = 1.0f / (1.0f + expf(-p1));
    float neg1 = -logf(1.0f - sp1 + 1e-12f) * 0.75f * sp1 * sp1;
    float pos1 = -logf(sp1 + 1e-12f) * 0.25f * (1.0f - sp1) * (1.0f - sp1);
    float clsc = pos1 - neg1;

    unsigned mykey[NLANE];
    float costv[NLANE];
#pragma unroll
    for (int l = 0; l < NLANE; l++){
        float ds = 1.0f - myDist[l] / mD + 0.01f;
        float ss = 1.0f - mySd[l]  / mS + 0.01f;
        float ts = 1.0f - myTh[l]  / mT + 0.01f;
        float prod = ds * ss * ts;
        float c = -(prod * prod) * 3.0f + clsc;
        c = (vL[l] > 0.0f) ? c : INFINITY;
        costv[l] = c;
        mykey[l] = fkey(c);
        s.key[l * NP + tid]  = mykey[l];
        s.iouc[l * NP + tid] = (vL[l] > 0.0f) ? fmaxf(myIou[l], 0.0f) : 0.0f;
    }
    int amin = 0;
    {
        float bc = costv[0];
#pragma unroll
        for (int l = 1; l < NLANE; l++){ if (costv[l] < bc){ bc = costv[l]; amin = l; } }
    }
    __syncthreads();

    // ---- warp-parallel top-4 per lane: min(cost keys) & max(iou), warps 0..3 ----
    if (wid < NLANE){
        const unsigned* kcol = s.key + wid * NP;
        unsigned s0 = 0xFFFFFFFFu, s1 = 0xFFFFFFFFu, s2 = 0xFFFFFFFFu, s3 = 0xFFFFFFFFu;
#pragma unroll
        for (int c = 0; c < 6; c++){
            unsigned x = kcol[c * 32 + lane];
            unsigned y = umn(s3, x);
            s3 = umx(s2, y); y = umn(s2, y);
            s2 = umx(s1, y); y = umn(s1, y);
            s1 = umx(s0, y); s0 = umn(s0, y);
        }
#pragma unroll
        for (int off = 16; off; off >>= 1){
            unsigned b0 = __shfl_xor_sync(0xffffffffu, s0, off);
            unsigned b1 = __shfl_xor_sync(0xffffffffu, s1, off);
            unsigned b2 = __shfl_xor_sync(0xffffffffu, s2, off);
            unsigned b3 = __shfl_xor_sync(0xffffffffu, s3, off);
            unsigned z0 = umn(s0, b3), z1 = umn(s1, b2), z2 = umn(s2, b1), z3 = umn(s3, b0);
            unsigned a;
            a = umn(z0, z2); z2 = umx(z0, z2); z0 = a;
            a = umn(z1, z3); z3 = umx(z1, z3); z1 = a;
            a = umn(z0, z1); z1 = umx(z0, z1); z0 = a;
            a = umn(z2, z3); z3 = umx(z2, z3); z2 = a;
            s0 = z0; s1 = z1; s2 = z2; s3 = z3;
        }
        const float* icol = s.iouc + wid * NP;
        float t0 = 0.f, t1 = 0.f, t2 = 0.f, t3 = 0.f;   // descending
#pragma unroll
        for (int c = 0; c < 6; c++){
            float x = icol[c * 32 + lane];
            float y = fmaxf(t3, x);
            t3 = fminf(t2, y); y = fmaxf(t2, y);
            t2 = fminf(t1, y); y = fmaxf(t1, y);
            t1 = fminf(t0, y); t0 = fmaxf(t0, y);
        }
#pragma unroll
        for (int off = 16; off; off >>= 1){
            float b0 = __shfl_xor_sync(0xffffffffu, t0, off);
            float b1 = __shfl_xor_sync(0xffffffffu, t1, off);
            float b2 = __shfl_xor_sync(0xffffffffu, t2, off);
            float b3 = __shfl_xor_sync(0xffffffffu, t3, off);
            float z0 = fmaxf(t0, b3), z1 = fmaxf(t1, b2), z2 = fmaxf(t2, b1), z3 = fmaxf(t3, b0);
            float a;
            a = fmaxf(z0, z2); z2 = fminf(z0, z2); z0 = a;
            a = fmaxf(z1, z3); z3 = fminf(z1, z3); z1 = a;
            a = fmaxf(z0, z1); z1 = fminf(z0, z1); z0 = a;
            a = fmaxf(z2, z3); z3 = fminf(z2, z3); z2 = a;
            t0 = z0; t1 = z1; t2 = z2; t3 = z3;
        }
        if (lane == 0){
            float sum = ((t0 + t1) + t2) + t3;
            int dk = (int)sum;                 // trunc == floor (sum >= 0)
            if (dk < 1) dk = 1; if (dk > 4) dk = 4;
            s.thr[wid] = (dk == 1) ? s0 : (dk == 2) ? s1 : (dk == 3) ? s2 : s3;
        }
    }
    __syncthreads();

    // ---- matching (rank < dyn_k  <=>  key <= dyn_k-th smallest) ----
    float Mf[NLANE]; int nM = 0;
#pragma unroll
    for (int l = 0; l < NLANE; l++){
        float m = 0.0f;
        if (vL[l] > 0.0f && mykey[l] <= s.thr[l]){ m = 1.0f; nM++; }
        Mf[l] = m;
    }
    if (nM > 1){ Mf[0] = 0.0f; Mf[amin] = 1.0f; }
    float mfsum = ((Mf[0] + Mf[1]) + Mf[2]) + Mf[3];
    int clsT = (mfsum > 0.0f) ? 1 : 0;

    // ---- focal ----
    float mxl = fmaxf(p0, p1);
    float e0 = expf(p0 - mxl), e1 = expf(p1 - mxl);
    float pt = ((clsT ? e1 : e0) / (e0 + e1)) + 1e-8f;
    float focal = -0.25f * (1.0f - pt) * (1.0f - pt) * logf(pt);

    // ---- reg + iou ----
    float yv = p2 * NSTRIPSF, xv = p3 * (IMGW - 1.0f), tv = p4 * 180.0f, lv = p5 * NSTRIPSF;
    float pstart = fminf(fmaxf(rintf(p2 * NSTRIPSF), 0.0f), NSTRIPSF);
    float regp = 0.0f, ioup = 0.0f;
#pragma unroll
    for (int l = 0; l < NLANE; l++){
        if (Mf[l] > 0.0f){
            const float* la = s.laneA + l * 8;
            float d1 = yv - la[2] * NSTRIPSF;
            float d2 = xv - la[3];
            float d3 = tv - la[4] * 180.0f;
            float tstart = rintf(la[2] * NSTRIPSF);
            float tlp = la[5] - (pstart - tstart);
            float d4 = lv - tlp;
            regp += smooth_l1(d1) + smooth_l1(d2) + smooth_l1(d3) + smooth_l1(d4);
            ioup += 1.0f - myIou[l];
        }
    }

    // ---- fused 4-way block sum ----
    float v0 = mfsum, v1 = focal, v2 = regp, v3 = ioup;
#pragma unroll
    for (int o2 = 16; o2; o2 >>= 1){
        v0 += __shfl_xor_sync(0xffffffffu, v0, o2);
        v1 += __shfl_xor_sync(0xffffffffu, v1, o2);
        v2 += __shfl_xor_sync(0xffffffffu, v2, o2);
        v3 += __shfl_xor_sync(0xffffffffu, v3, o2);
    }
    __syncthreads();   // red[] was read above; protect reuse
    if (lane == 0){ s.red[wid] = v0; s.red[8 + wid] = v1; s.red[16 + wid] = v2; s.red[24 + wid] = v3; }
    __syncthreads();
    if (tid == 0){
        float nmatch = 0.f, focal_s = 0.f, reg_s = 0.f, iou_s = 0.f;
#pragma unroll
        for (int w = 0; w < 6; w++){
            nmatch  += s.red[w];
            focal_s += s.red[8 + w];
            reg_s   += s.red[16 + w];
            iou_s   += s.red[24 + w];
        }
        float cls_term = focal_s / (has_t ? num_t : 1.0f);
        float reg_term = has_t ? reg_s / fmaxf(nmatch * 4.0f, 1.0f) : 0.0f;
        float iou_term = has_t ? iou_s / fmaxf(nmatch, 1.0f) : 0.0f;
        g_partials[blk] = 2.0f * cls_term + 0.2f * reg_term + 2.0f * iou_term;
    }
}

__global__ void clr_reduce(const float* __restrict__ seg, float* __restrict__ out)
{
    __shared__ float sred[512];
    int tid = threadIdx.x;
    float v = 0.0f;
    for (int i = tid; i < NBLK; i += 512) v += g_partials[i];
    sred[tid] = v;
    __syncthreads();
    for (int o = 256; o; o >>= 1){
        if (tid < o) sred[tid] += sred[tid + o];
        __syncthreads();
    }
    if (tid == 0) out[0] = sred[0] / (float)NBLK + seg[0];
}

extern "C" void kernel_launch(void* const* d_in, const int* in_sizes, int n_in,
                              void* d_out, int out_size)
{
    const float* pred = (const float*)d_in[0];
    const float* tgt  = (const float*)d_in[1];
    const float* seg  = (const float*)d_in[2];
    float* out = (float*)d_out;

    static int attr_set = 0;
    const int smem = (int)sizeof(SMLayout);
    if (!attr_set){
        cudaFuncSetAttribute(clr_main, cudaFuncAttributeMaxDynamicSharedMemorySize, smem);
        attr_set = 1;
    }
    clr_main<<<NBLK, 192, smem>>>(pred, tgt);
    clr_reduce<<<1, 512>>>(seg, out);
}

// round 3
// speedup vs baseline: 2.4934x; 1.1528x over previous
#include <cuda_runtime.h>
#include <math.h>

#define NPTS     72
#define NSTRIPSF 71.0f
#define NLANE    4
#define NP       192
#define BATCH    512
#define DD       78
#define NBLK     1536
#define IMGW     800.0f
#define IMGH     320.0f
#define XPITCH   73
#define SPITCH   7

__device__ float    g_partials[NBLK];
__device__ unsigned g_count = 0;

__device__ __forceinline__ unsigned umn(unsigned a, unsigned b){ return a < b ? a : b; }
__device__ __forceinline__ unsigned umx(unsigned a, unsigned b){ return a > b ? a : b; }
__device__ __forceinline__ unsigned fkey(float f){
    int b = __float_as_int(f);
    return (b >= 0) ? ((unsigned)b ^ 0x80000000u) : ~((unsigned)b);
}
__device__ __forceinline__ float smooth_l1(float x){
    float a = fabsf(x);
    return (a < 1.0f) ? 0.5f * x * x : a - 0.5f;
}

struct __align__(16) SMLayout {
    float    xs[NP * XPITCH];     // pred xs premultiplied by 799
    float    scal[NP * SPITCH];   // p0..p5
    float    tx[NLANE * NPTS];    // raw target xs per lane
    unsigned key[NLANE * NP];     // cost order-keys, lane-major
    float    iouc[NLANE * NP];    // clamped iou_sg, lane-major
    float    laneA[NLANE * 8];    // [0]=valid [1]=nv [2..5]=t2..5 [6]=30*nv
    int      startL[NLANE], endL[NLANE];
    unsigned k4[NLANE][4];        // 4 smallest cost keys per lane
    int      dks[NLANE];          // dyn_k per lane
    unsigned thr[NLANE];
    float    red[32];
    int      lastFlag;
};

__global__ void __launch_bounds__(192)
clr_main(const float* __restrict__ predA, const float* __restrict__ tgtA,
         const float* __restrict__ seg, float* __restrict__ out)
{
    extern __shared__ char smraw[];
    SMLayout& s = *reinterpret_cast<SMLayout*>(smraw);

    const int tid  = threadIdx.x;
    const int wid  = tid >> 5;
    const int lane = tid & 31;
    const int blk  = blockIdx.x;
    const int b    = blk & (BATCH - 1);

    const float2* pred2 = (const float2*)(predA + (size_t)blk * (NP * DD));
    const float*  tgt   = tgtA + (size_t)b * (NLANE * DD);

    // ---- stage predictions (coalesced float2) ----
#pragma unroll 4
    for (int k = 0; k < 39; k++){
        int idx = tid + k * 192;
        int r = idx / 39, c2 = idx - r * 39;
        float2 v = pred2[idx];
        if (c2 < 3){
            s.scal[r * SPITCH + 2 * c2]     = v.x;
            s.scal[r * SPITCH + 2 * c2 + 1] = v.y;
        } else {
            int c = 2 * c2 - 6;
            s.xs[r * XPITCH + c]     = v.x * (IMGW - 1.0f);
            s.xs[r * XPITCH + c + 1] = v.y * (IMGW - 1.0f);
        }
    }

    // ---- stage targets, find contiguous valid run per lane (warps 0..3) ----
    if (wid < NLANE){
        const float* t = tgt + wid * DD;
        unsigned m[3];
#pragma unroll
        for (int c = 0; c < 3; c++){
            int j = c * 32 + lane;
            float x = (j < NPTS) ? t[6 + j] : -1.0f;
            if (j < NPTS) s.tx[wid * NPTS + j] = x;
            m[c] = __ballot_sync(0xffffffffu, (x >= 0.0f) && (x < IMGW));
        }
        if (lane == 0){
            int nv = __popc(m[0]) + __popc(m[1]) + __popc(m[2]);
            int st = m[0] ? (__ffs(m[0]) - 1) : (m[1] ? (31 + __ffs(m[1])) : (m[2] ? (63 + __ffs(m[2])) : 0));
            int en = m[2] ? (96 - __clz(m[2])) : (m[1] ? (64 - __clz(m[1])) : (m[0] ? (32 - __clz(m[0])) : 0));
            s.startL[wid] = st; s.endL[wid] = en;
            float* la = s.laneA + wid * 8;
            la[0] = (t[1] == 1.0f) ? 1.0f : 0.0f;
            la[1] = (float)nv;
            la[2] = t[2]; la[3] = t[3]; la[4] = t[4]; la[5] = t[5];
            la[6] = 30.0f * (float)nv;
        }
    }
    __syncthreads();

    // ---- per-prior: S = sum |px - tx| over the valid run ----
    const float* myxs = s.xs + tid * XPITCH;
    float myIou[NLANE], myDist[NLANE];
#pragma unroll
    for (int l = 0; l < NLANE; l++){
        const int st = s.startL[l], en = s.endL[l];
        const float* txl = s.tx + l * NPTS;
        float a0 = 0.0f, a1 = 0.0f;
        int j = st;
#pragma unroll 4
        for (; j + 1 < en; j += 2){
            a0 += fabsf(myxs[j]     - txl[j]);
            a1 += fabsf(myxs[j + 1] - txl[j + 1]);
        }
        if (j < en) a0 += fabsf(myxs[j] - txl[j]);
        float S = a0 + a1;
        float nv30 = s.laneA[l * 8 + 6];
        myIou[l]  = (nv30 - S) / (nv30 + S + 1e-9f);
        myDist[l] = S / (s.laneA[l * 8 + 1] + 1e-9f);
    }

    // ---- per-lane geometric scores + local maxima ----
    const float* ps = s.scal + tid * SPITCH;
    const float p0 = ps[0], p1 = ps[1], p2 = ps[2], p3 = ps[3], p4 = ps[4], p5 = ps[5];
    float vL[NLANE], mySd[NLANE], myTh[NLANE];
    float lmD = -INFINITY, lmS = -INFINITY, lmT = -INFINITY;
    const float py = p2 * (IMGH - 1.0f), pxc = p3 * (IMGW - 1.0f);
#pragma unroll
    for (int l = 0; l < NLANE; l++){
        const float* la = s.laneA + l * 8;
        float v = la[0]; vL[l] = v;
        float dy = py - la[2] * (IMGH - 1.0f);
        float dx = pxc - la[3];
        float sd = sqrtf(dy * dy + dx * dx);
        mySd[l] = sd;
        float th = fabsf(p4 - la[4]) * 180.0f;
        myTh[l] = th;
        if (v > 0.0f){
            lmD = fmaxf(lmD, myDist[l]);
            lmS = fmaxf(lmS, sd);
            lmT = fmaxf(lmT, th);
        }
    }
    const float num_t = vL[0] + vL[1] + vL[2] + vL[3];
    const bool  has_t = num_t > 0.0f;

    // ---- fused 3-way block max ----
#pragma unroll
    for (int o2 = 16; o2; o2 >>= 1){
        lmD = fmaxf(lmD, __shfl_xor_sync(0xffffffffu, lmD, o2));
        lmS = fmaxf(lmS, __shfl_xor_sync(0xffffffffu, lmS, o2));
        lmT = fmaxf(lmT, __shfl_xor_sync(0xffffffffu, lmT, o2));
    }
    if (lane == 0){ s.red[wid] = lmD; s.red[8 + wid] = lmS; s.red[16 + wid] = lmT; }
    __syncthreads();
    float mD = s.red[0], mS = s.red[8], mT = s.red[16];
#pragma unroll
    for (int w = 1; w < 6; w++){
        mD = fmaxf(mD, s.red[w]);
        mS = fmaxf(mS, s.red[8 + w]);
        mT = fmaxf(mT, s.red[16 + w]);
    }
    if (!has_t){ mD = 1.0f; mS = 1.0f; mT = 1.0f; }

    // ---- classification cost + cost matrix keys ----
    float sp1  = 1.0f / (1.0f + expf(-p1));
    float neg1 = -logf(1.0f - sp1 + 1e-12f) * 0.75f * sp1 * sp1;
    float pos1 = -logf(sp1 + 1e-12f) * 0.25f * (1.0f - sp1) * (1.0f - sp1);
    float clsc = pos1 - neg1;

    unsigned mykey[NLANE];
    float costv[NLANE];
#pragma unroll
    for (int l = 0; l < NLANE; l++){
        float ds = 1.0f - myDist[l] / mD + 0.01f;
        float ss = 1.0f - mySd[l]  / mS + 0.01f;
        float ts = 1.0f - myTh[l]  / mT + 0.01f;
        float prod = ds * ss * ts;
        float c = -(prod * prod) * 3.0f + clsc;
        c = (vL[l] > 0.0f) ? c : INFINITY;
        costv[l] = c;
        mykey[l] = fkey(c);
        s.key[l * NP + tid]  = mykey[l];
        s.iouc[l * NP + tid] = (vL[l] > 0.0f) ? fmaxf(myIou[l], 0.0f) : 0.0f;
    }
    int amin = 0;
    {
        float bc = costv[0];
#pragma unroll
        for (int l = 1; l < NLANE; l++){ if (costv[l] < bc){ bc = costv[l]; amin = l; } }
    }
    __syncthreads();

    // ---- warps 0-3: 4 smallest cost keys of lane wid ----
    if (wid < NLANE){
        const unsigned* kcol = s.key + wid * NP;
        unsigned s0 = 0xFFFFFFFFu, s1 = 0xFFFFFFFFu, s2 = 0xFFFFFFFFu, s3 = 0xFFFFFFFFu;
#pragma unroll
        for (int c = 0; c < 6; c++){
            unsigned x = kcol[c * 32 + lane];
            unsigned y = umn(s3, x);
            s3 = umx(s2, y); y = umn(s2, y);
            s2 = umx(s1, y); y = umn(s1, y);
            s1 = umx(s0, y); s0 = umn(s0, y);
        }
#pragma unroll
        for (int off = 16; off; off >>= 1){
            unsigned b0 = __shfl_xor_sync(0xffffffffu, s0, off);
            unsigned b1 = __shfl_xor_sync(0xffffffffu, s1, off);
            unsigned b2 = __shfl_xor_sync(0xffffffffu, s2, off);
            unsigned b3 = __shfl_xor_sync(0xffffffffu, s3, off);
            unsigned z0 = umn(s0, b3), z1 = umn(s1, b2), z2 = umn(s2, b1), z3 = umn(s3, b0);
            unsigned a;
            a = umn(z0, z2); z2 = umx(z0, z2); z0 = a;
            a = umn(z1, z3); z3 = umx(z1, z3); z1 = a;
            a = umn(z0, z1); z1 = umx(z0, z1); z0 = a;
            a = umn(z2, z3); z3 = umx(z2, z3); z2 = a;
            s0 = z0; s1 = z1; s2 = z2; s3 = z3;
        }
        if (lane == 0){
            s.k4[wid][0] = s0; s.k4[wid][1] = s1; s.k4[wid][2] = s2; s.k4[wid][3] = s3;
        }
    } else {
        // ---- warps 4-5: top-4 iou (2 lanes each) -> dyn_k ----
#pragma unroll
        for (int q = 0; q < 2; q++){
            int l = (wid - 4) * 2 + q;
            const float* icol = s.iouc + l * NP;
            float t0 = 0.f, t1 = 0.f, t2 = 0.f, t3 = 0.f;
#pragma unroll
            for (int c = 0; c < 6; c++){
                float x = icol[c * 32 + lane];
                float y = fmaxf(t3, x);
                t3 = fminf(t2, y); y = fmaxf(t2, y);
                t2 = fminf(t1, y); y = fmaxf(t1, y);
                t1 = fminf(t0, y); t0 = fmaxf(t0, y);
            }
#pragma unroll
            for (int off = 16; off; off >>= 1){
                float b0 = __shfl_xor_sync(0xffffffffu, t0, off);
                float b1 = __shfl_xor_sync(0xffffffffu, t1, off);
                float b2 = __shfl_xor_sync(0xffffffffu, t2, off);
                float b3 = __shfl_xor_sync(0xffffffffu, t3, off);
                float z0 = fmaxf(t0, b3), z1 = fmaxf(t1, b2), z2 = fmaxf(t2, b1), z3 = fmaxf(t3, b0);
                float a;
                a = fmaxf(z0, z2); z2 = fminf(z0, z2); z0 = a;
                a = fmaxf(z1, z3); z3 = fminf(z1, z3); z1 = a;
                a = fmaxf(z0, z1); z1 = fminf(z0, z1); z0 = a;
                a = fmaxf(z2, z3); z3 = fminf(z2, z3); z2 = a;
                t0 = z0; t1 = z1; t2 = z2; t3 = z3;
            }
            if (lane == 0){
                float sum = ((t0 + t1) + t2) + t3;
                int dk = (int)sum;
                if (dk < 1) dk = 1; if (dk > 4) dk = 4;
                s.dks[l] = dk;
            }
        }
    }
    __syncthreads();
    if (tid < NLANE) s.thr[tid] = s.k4[tid][s.dks[tid] - 1];
    __syncthreads();

    // ---- matching ----
    float Mf[NLANE]; int nM = 0;
#pragma unroll
    for (int l = 0; l < NLANE; l++){
        float m = 0.0f;
        if (vL[l] > 0.0f && mykey[l] <= s.thr[l]){ m = 1.0f; nM++; }
        Mf[l] = m;
    }
    if (nM > 1){ Mf[0] = 0.0f; Mf[amin] = 1.0f; }
    float mfsum = ((Mf[0] + Mf[1]) + Mf[2]) + Mf[3];
    int clsT = (mfsum > 0.0f) ? 1 : 0;

    // ---- focal ----
    float mxl = fmaxf(p0, p1);
    float e0 = expf(p0 - mxl), e1 = expf(p1 - mxl);
    float pt = ((clsT ? e1 : e0) / (e0 + e1)) + 1e-8f;
    float focal = -0.25f * (1.0f - pt) * (1.0f - pt) * logf(pt);

    // ---- reg + iou ----
    float yv = p2 * NSTRIPSF, xv = p3 * (IMGW - 1.0f), tv = p4 * 180.0f, lv = p5 * NSTRIPSF;
    float pstart = fminf(fmaxf(rintf(p2 * NSTRIPSF), 0.0f), NSTRIPSF);
    float regp = 0.0f, ioup = 0.0f;
#pragma unroll
    for (int l = 0; l < NLANE; l++){
        if (Mf[l] > 0.0f){
            const float* la = s.laneA + l * 8;
            float d1 = yv - la[2] * NSTRIPSF;
            float d2 = xv - la[3];
            float d3 = tv - la[4] * 180.0f;
            float tstart = rintf(la[2] * NSTRIPSF);
            float tlp = la[5] - (pstart - tstart);
            float d4 = lv - tlp;
            regp += smooth_l1(d1) + smooth_l1(d2) + smooth_l1(d3) + smooth_l1(d4);
            ioup += 1.0f - myIou[l];
        }
    }

    // ---- fused 4-way block sum ----
    float v0 = mfsum, v1 = focal, v2 = regp, v3 = ioup;
#pragma unroll
    for (int o2 = 16; o2; o2 >>= 1){
        v0 += __shfl_xor_sync(0xffffffffu, v0, o2);
        v1 += __shfl_xor_sync(0xffffffffu, v1, o2);
        v2 += __shfl_xor_sync(0xffffffffu, v2, o2);
        v3 += __shfl_xor_sync(0xffffffffu, v3, o2);
    }
    __syncthreads();
    if (lane == 0){ s.red[wid] = v0; s.red[8 + wid] = v1; s.red[16 + wid] = v2; s.red[24 + wid] = v3; }
    __syncthreads();
    if (tid == 0){
        float nmatch = 0.f, focal_s = 0.f, reg_s = 0.f, iou_s = 0.f;
#pragma unroll
        for (int w = 0; w < 6; w++){
            nmatch  += s.red[w];
            focal_s += s.red[8 + w];
            reg_s   += s.red[16 + w];
            iou_s   += s.red[24 + w];
        }
        float cls_term = focal_s / (has_t ? num_t : 1.0f);
        float reg_term = has_t ? reg_s / fmaxf(nmatch * 4.0f, 1.0f) : 0.0f;
        float iou_term = has_t ? iou_s / fmaxf(nmatch, 1.0f) : 0.0f;
        g_partials[blk] = 2.0f * cls_term + 0.2f * reg_term + 2.0f * iou_term;

        __threadfence();
        unsigned prev = atomicAdd(&g_count, 1u);
        s.lastFlag = (prev == NBLK - 1) ? 1 : 0;
    }
    __syncthreads();

    // ---- last block: deterministic final reduction ----
    if (s.lastFlag){
        __threadfence();
        float acc = 0.0f;
#pragma unroll
        for (int k = 0; k < 8; k++)                   // fixed order: 8 strided reads
            acc += g_partials[tid + k * 192];
#pragma unroll
        for (int o2 = 16; o2; o2 >>= 1)
            acc += __shfl_xor_sync(0xffffffffu, acc, o2);
        __syncthreads();
        if (lane == 0) s.red[wid] = acc;
        __syncthreads();
        if (tid == 0){
            float tot = 0.0f;
#pragma unroll
            for (int w = 0; w < 6; w++) tot += s.red[w];
            out[0] = tot / (float)NBLK + seg[0];
            g_count = 0;                               // self-reset for graph replay
        }
    }
}

extern "C" void kernel_launch(void* const* d_in, const int* in_sizes, int n_in,
                              void* d_out, int out_size)
{
    const float* pred = (const float*)d_in[0];
    const float* tgt  = (const float*)d_in[1];
    const float* seg  = (const float*)d_in[2];
    float* out = (float*)d_out;

    static int attr_set = 0;
    const int smem = (int)sizeof(SMLayout);
    if (!attr_set){
        cudaFuncSetAttribute(clr_main, cudaFuncAttributeMaxDynamicSharedMemorySize, smem);
        attr_set = 1;
    }
    clr_main<<<NBLK, 192, smem>>>(pred, tgt, seg, out);
}

// round 4
// speedup vs baseline: 3.0100x; 1.2072x over previous
#include <cuda_runtime.h>
#include <math.h>

#define NPTS     72
#define NSTRIPSF 71.0f
#define NLANE    4
#define NP       192
#define BATCH    512
#define DD       78
#define NBLK     1536
#define IMGW     800.0f
#define IMGH     320.0f
#define XPITCH   73
#define SPITCH   7
#define NT       384

__device__ float    g_partials[NBLK];
__device__ unsigned g_count = 0;

__device__ __forceinline__ unsigned umn(unsigned a, unsigned b){ return a < b ? a : b; }
__device__ __forceinline__ unsigned umx(unsigned a, unsigned b){ return a > b ? a : b; }
__device__ __forceinline__ unsigned fkey(float f){
    int b = __float_as_int(f);
    return (b >= 0) ? ((unsigned)b ^ 0x80000000u) : ~((unsigned)b);
}
__device__ __forceinline__ float smooth_l1(float x){
    float a = fabsf(x);
    return (a < 1.0f) ? 0.5f * x * x : a - 0.5f;
}
// partial barrier over threads 0..191 (warps 0-5)
__device__ __forceinline__ void barL(){
    asm volatile("bar.sync 1, 192;" ::: "memory");
}

struct __align__(16) SMLayout {
    float    xs[NP * XPITCH];     // pred xs premultiplied by 799, row per prior
    float    scal[NP * SPITCH];   // p0..p5
    float    tx[NLANE * NPTS];    // raw target xs per lane
    unsigned key[NLANE * NP];     // PHASE A: scratch for upper-half S partials; PHASE B: cost keys
    float    iouc[NLANE * NP];    // clamped iou_sg, lane-major
    float    laneA[NLANE * 8];    // [0]=valid [1]=nv [2..5]=t2..5 [6]=30*nv
    int      startL[NLANE], endL[NLANE];
    unsigned k4[NLANE][4];
    int      dks[NLANE];
    unsigned thr[NLANE];
    float    red[32];
    int      lastFlag;
};

__global__ void __launch_bounds__(NT, 3)
clr_main(const float* __restrict__ predA, const float* __restrict__ tgtA,
         const float* __restrict__ seg, float* __restrict__ out)
{
    extern __shared__ char smraw[];
    SMLayout& s = *reinterpret_cast<SMLayout*>(smraw);

    const int tid  = threadIdx.x;
    const int wid  = tid >> 5;
    const int lane = tid & 31;
    const int p    = (tid < NP) ? tid : tid - NP;   // prior index
    const int half = (tid < NP) ? 0 : 1;            // j-range half
    const int blk  = blockIdx.x;
    const int b    = blk & (BATCH - 1);

    const float2* pred2 = (const float2*)(predA + (size_t)blk * (NP * DD));
    const float*  tgt   = tgtA + (size_t)b * (NLANE * DD);

    // ---- stage predictions (coalesced float2, 384 threads) ----
#pragma unroll 4
    for (int k = 0; k < 20; k++){
        int idx = tid + k * NT;
        if (idx < 7488){
            int r = idx / 39, c2 = idx - r * 39;
            float2 v = pred2[idx];
            if (c2 < 3){
                s.scal[r * SPITCH + 2 * c2]     = v.x;
                s.scal[r * SPITCH + 2 * c2 + 1] = v.y;
            } else {
                int c = 2 * c2 - 6;
                s.xs[r * XPITCH + c]     = v.x * (IMGW - 1.0f);
                s.xs[r * XPITCH + c + 1] = v.y * (IMGW - 1.0f);
            }
        }
    }

    // ---- stage targets, find contiguous valid run per lane (warps 0..3) ----
    if (wid < NLANE){
        const float* t = tgt + wid * DD;
        unsigned m[3];
#pragma unroll
        for (int c = 0; c < 3; c++){
            int j = c * 32 + lane;
            float x = (j < NPTS) ? t[6 + j] : -1.0f;
            if (j < NPTS) s.tx[wid * NPTS + j] = x;
            m[c] = __ballot_sync(0xffffffffu, (x >= 0.0f) && (x < IMGW));
        }
        if (lane == 0){
            int nv = __popc(m[0]) + __popc(m[1]) + __popc(m[2]);
            int st = m[0] ? (__ffs(m[0]) - 1) : (m[1] ? (31 + __ffs(m[1])) : (m[2] ? (63 + __ffs(m[2])) : 0));
            int en = m[2] ? (96 - __clz(m[2])) : (m[1] ? (64 - __clz(m[1])) : (m[0] ? (32 - __clz(m[0])) : 0));
            s.startL[wid] = st; s.endL[wid] = en;
            float* la = s.laneA + wid * 8;
            la[0] = (t[1] == 1.0f) ? 1.0f : 0.0f;
            la[1] = (float)nv;
            la[2] = t[2]; la[3] = t[3]; la[4] = t[4]; la[5] = t[5];
            la[6] = 30.0f * (float)nv;
        }
    }
    __syncthreads();

    // ---- S half-loop: all 384 threads; thread (p, half) sums its j-half ----
    const float* myxs = s.xs + p * XPITCH;
    float aS[NLANE];
#pragma unroll
    for (int l = 0; l < NLANE; l++){
        const int st0 = s.startL[l], en0 = s.endL[l];
        const int mid = (st0 + en0) >> 1;
        const int st  = half ? mid : st0;
        const int en  = half ? en0 : mid;
        const float* txl = s.tx + l * NPTS;
        float a0 = 0.0f, a1 = 0.0f;
        int j = st;
#pragma unroll 4
        for (; j + 1 < en; j += 2){
            a0 += fabsf(myxs[j]     - txl[j]);
            a1 += fabsf(myxs[j + 1] - txl[j + 1]);
        }
        if (j < en) a0 += fabsf(myxs[j] - txl[j]);
        aS[l] = a0 + a1;
    }
    float* scratch = (float*)s.key;
    if (half){
#pragma unroll
        for (int l = 0; l < NLANE; l++) scratch[l * NP + p] = aS[l];
    }
    __syncthreads();
    if (tid >= NP) return;          // upper warps done; lower uses named barriers only

    // ================= PHASE B: threads 0..191 =================
    float myIou[NLANE], myDist[NLANE];
#pragma unroll
    for (int l = 0; l < NLANE; l++){
        float S = aS[l] + scratch[l * NP + tid];
        float nv30 = s.laneA[l * 8 + 6];
        myIou[l]  = (nv30 - S) / (nv30 + S + 1e-9f);
        myDist[l] = S / (s.laneA[l * 8 + 1] + 1e-9f);
    }

    const float* ps = s.scal + tid * SPITCH;
    const float p0 = ps[0], p1 = ps[1], p2 = ps[2], p3 = ps[3], p4 = ps[4], p5 = ps[5];
    float vL[NLANE], mySd[NLANE], myTh[NLANE];
    float lmD = -INFINITY, lmS = -INFINITY, lmT = -INFINITY;
    const float py = p2 * (IMGH - 1.0f), pxc = p3 * (IMGW - 1.0f);
#pragma unroll
    for (int l = 0; l < NLANE; l++){
        const float* la = s.laneA + l * 8;
        float v = la[0]; vL[l] = v;
        float dy = py - la[2] * (IMGH - 1.0f);
        float dx = pxc - la[3];
        float sd = sqrtf(dy * dy + dx * dx);
        mySd[l] = sd;
        float th = fabsf(p4 - la[4]) * 180.0f;
        myTh[l] = th;
        if (v > 0.0f){
            lmD = fmaxf(lmD, myDist[l]);
            lmS = fmaxf(lmS, sd);
            lmT = fmaxf(lmT, th);
        }
    }
    const float num_t = vL[0] + vL[1] + vL[2] + vL[3];
    const bool  has_t = num_t > 0.0f;

    // fused 3-way block max over 192 threads
#pragma unroll
    for (int o2 = 16; o2; o2 >>= 1){
        lmD = fmaxf(lmD, __shfl_xor_sync(0xffffffffu, lmD, o2));
        lmS = fmaxf(lmS, __shfl_xor_sync(0xffffffffu, lmS, o2));
        lmT = fmaxf(lmT, __shfl_xor_sync(0xffffffffu, lmT, o2));
    }
    if (lane == 0){ s.red[wid] = lmD; s.red[8 + wid] = lmS; s.red[16 + wid] = lmT; }
    barL();
    float mD = s.red[0], mS = s.red[8], mT = s.red[16];
#pragma unroll
    for (int w = 1; w < 6; w++){
        mD = fmaxf(mD, s.red[w]);
        mS = fmaxf(mS, s.red[8 + w]);
        mT = fmaxf(mT, s.red[16 + w]);
    }
    if (!has_t){ mD = 1.0f; mS = 1.0f; mT = 1.0f; }

    // classification cost + cost keys  (NOTE: key[] scratch reads for this tid
    // are complete; each thread overwrites only its own key[l*NP+tid])
    float sp1  = 1.0f / (1.0f + expf(-p1));
    float neg1 = -logf(1.0f - sp1 + 1e-12f) * 0.75f * sp1 * sp1;
    float pos1 = -logf(sp1 + 1e-12f) * 0.25f * (1.0f - sp1) * (1.0f - sp1);
    float clsc = pos1 - neg1;

    unsigned mykey[NLANE];
    float costv[NLANE];
#pragma unroll
    for (int l = 0; l < NLANE; l++){
        float ds = 1.0f - myDist[l] / mD + 0.01f;
        float ss = 1.0f - mySd[l]  / mS + 0.01f;
        float ts = 1.0f - myTh[l]  / mT + 0.01f;
        float prod = ds * ss * ts;
        float c = -(prod * prod) * 3.0f + clsc;
        c = (vL[l] > 0.0f) ? c : INFINITY;
        costv[l] = c;
        mykey[l] = fkey(c);
        s.key[l * NP + tid]  = mykey[l];
        s.iouc[l * NP + tid] = (vL[l] > 0.0f) ? fmaxf(myIou[l], 0.0f) : 0.0f;
    }
    int amin = 0;
    {
        float bc = costv[0];
#pragma unroll
        for (int l = 1; l < NLANE; l++){ if (costv[l] < bc){ bc = costv[l]; amin = l; } }
    }
    barL();

    // warps 0-3: 4 smallest cost keys of lane wid; warps 4-5: top-4 iou -> dyn_k
    if (wid < NLANE){
        const unsigned* kcol = s.key + wid * NP;
        unsigned s0 = 0xFFFFFFFFu, s1 = 0xFFFFFFFFu, s2 = 0xFFFFFFFFu, s3 = 0xFFFFFFFFu;
#pragma unroll
        for (int c = 0; c < 6; c++){
            unsigned x = kcol[c * 32 + lane];
            unsigned y = umn(s3, x);
            s3 = umx(s2, y); y = umn(s2, y);
            s2 = umx(s1, y); y = umn(s1, y);
            s1 = umx(s0, y); s0 = umn(s0, y);
        }
#pragma unroll
        for (int off = 16; off; off >>= 1){
            unsigned b0 = __shfl_xor_sync(0xffffffffu, s0, off);
            unsigned b1 = __shfl_xor_sync(0xffffffffu, s1, off);
            unsigned b2 = __shfl_xor_sync(0xffffffffu, s2, off);
            unsigned b3 = __shfl_xor_sync(0xffffffffu, s3, off);
            unsigned z0 = umn(s0, b3), z1 = umn(s1, b2), z2 = umn(s2, b1), z3 = umn(s3, b0);
            unsigned a;
            a = umn(z0, z2); z2 = umx(z0, z2); z0 = a;
            a = umn(z1, z3); z3 = umx(z1, z3); z1 = a;
            a = umn(z0, z1); z1 = umx(z0, z1); z0 = a;
            a = umn(z2, z3); z3 = umx(z2, z3); z2 = a;
            s0 = z0; s1 = z1; s2 = z2; s3 = z3;
        }
        if (lane == 0){
            s.k4[wid][0] = s0; s.k4[wid][1] = s1; s.k4[wid][2] = s2; s.k4[wid][3] = s3;
        }
    } else {
#pragma unroll
        for (int q = 0; q < 2; q++){
            int l = (wid - 4) * 2 + q;
            const float* icol = s.iouc + l * NP;
            float t0 = 0.f, t1 = 0.f, t2 = 0.f, t3 = 0.f;
#pragma unroll
            for (int c = 0; c < 6; c++){
                float x = icol[c * 32 + lane];
                float y = fmaxf(t3, x);
                t3 = fminf(t2, y); y = fmaxf(t2, y);
                t2 = fminf(t1, y); y = fmaxf(t1, y);
                t1 = fminf(t0, y); t0 = fmaxf(t0, y);
            }
#pragma unroll
            for (int off = 16; off; off >>= 1){
                float b0 = __shfl_xor_sync(0xffffffffu, t0, off);
                float b1 = __shfl_xor_sync(0xffffffffu, t1, off);
                float b2 = __shfl_xor_sync(0xffffffffu, t2, off);
                float b3 = __shfl_xor_sync(0xffffffffu, t3, off);
                float z0 = fmaxf(t0, b3), z1 = fmaxf(t1, b2), z2 = fmaxf(t2, b1), z3 = fmaxf(t3, b0);
                float a;
                a = fmaxf(z0, z2); z2 = fminf(z0, z2); z0 = a;
                a = fmaxf(z1, z3); z3 = fminf(z1, z3); z1 = a;
                a = fmaxf(z0, z1); z1 = fminf(z0, z1); z0 = a;
                a = fmaxf(z2, z3); z3 = fminf(z2, z3); z2 = a;
                t0 = z0; t1 = z1; t2 = z2; t3 = z3;
            }
            if (lane == 0){
                float sum = ((t0 + t1) + t2) + t3;
                int dk = (int)sum;
                if (dk < 1) dk = 1; if (dk > 4) dk = 4;
                s.dks[l] = dk;
            }
        }
    }
    barL();
    if (tid < NLANE) s.thr[tid] = s.k4[tid][s.dks[tid] - 1];
    barL();

    // matching
    float Mf[NLANE]; int nM = 0;
#pragma unroll
    for (int l = 0; l < NLANE; l++){
        float m = 0.0f;
        if (vL[l] > 0.0f && mykey[l] <= s.thr[l]){ m = 1.0f; nM++; }
        Mf[l] = m;
    }
    if (nM > 1){ Mf[0] = 0.0f; Mf[amin] = 1.0f; }
    float mfsum = ((Mf[0] + Mf[1]) + Mf[2]) + Mf[3];
    int clsT = (mfsum > 0.0f) ? 1 : 0;

    // focal
    float mxl = fmaxf(p0, p1);
    float e0 = expf(p0 - mxl), e1 = expf(p1 - mxl);
    float pt = ((clsT ? e1 : e0) / (e0 + e1)) + 1e-8f;
    float focal = -0.25f * (1.0f - pt) * (1.0f - pt) * logf(pt);

    // reg + iou
    float yv = p2 * NSTRIPSF, xv = p3 * (IMGW - 1.0f), tv = p4 * 180.0f, lv = p5 * NSTRIPSF;
    float pstart = fminf(fmaxf(rintf(p2 * NSTRIPSF), 0.0f), NSTRIPSF);
    float regp = 0.0f, ioup = 0.0f;
#pragma unroll
    for (int l = 0; l < NLANE; l++){
        if (Mf[l] > 0.0f){
            const float* la = s.laneA + l * 8;
            float d1 = yv - la[2] * NSTRIPSF;
            float d2 = xv - la[3];
            float d3 = tv - la[4] * 180.0f;
            float tstart = rintf(la[2] * NSTRIPSF);
            float tlp = la[5] - (pstart - tstart);
            float d4 = lv - tlp;
            regp += smooth_l1(d1) + smooth_l1(d2) + smooth_l1(d3) + smooth_l1(d4);
            ioup += 1.0f - myIou[l];
        }
    }

    // fused 4-way block sum over 192 threads
    float v0 = mfsum, v1 = focal, v2 = regp, v3 = ioup;
#pragma unroll
    for (int o2 = 16; o2; o2 >>= 1){
        v0 += __shfl_xor_sync(0xffffffffu, v0, o2);
        v1 += __shfl_xor_sync(0xffffffffu, v1, o2);
        v2 += __shfl_xor_sync(0xffffffffu, v2, o2);
        v3 += __shfl_xor_sync(0xffffffffu, v3, o2);
    }
    barL();
    if (lane == 0){ s.red[wid] = v0; s.red[8 + wid] = v1; s.red[16 + wid] = v2; s.red[24 + wid] = v3; }
    barL();
    if (tid == 0){
        float nmatch = 0.f, focal_s = 0.f, reg_s = 0.f, iou_s = 0.f;
#pragma unroll
        for (int w = 0; w < 6; w++){
            nmatch  += s.red[w];
            focal_s += s.red[8 + w];
            reg_s   += s.red[16 + w];
            iou_s   += s.red[24 + w];
        }
        float cls_term = focal_s / (has_t ? num_t : 1.0f);
        float reg_term = has_t ? reg_s / fmaxf(nmatch * 4.0f, 1.0f) : 0.0f;
        float iou_term = has_t ? iou_s / fmaxf(nmatch, 1.0f) : 0.0f;
        g_partials[blk] = 2.0f * cls_term + 0.2f * reg_term + 2.0f * iou_term;

        __threadfence();
        unsigned prev = atomicAdd(&g_count, 1u);
        s.lastFlag = (prev == NBLK - 1) ? 1 : 0;
    }
    barL();

    // last block: deterministic final reduction (threads 0..191)
    if (s.lastFlag){
        __threadfence();
        float acc = 0.0f;
#pragma unroll
        for (int k = 0; k < 8; k++)
            acc += g_partials[tid + k * 192];
#pragma unroll
        for (int o2 = 16; o2; o2 >>= 1)
            acc += __shfl_xor_sync(0xffffffffu, acc, o2);
        barL();
        if (lane == 0) s.red[wid] = acc;
        barL();
        if (tid == 0){
            float tot = 0.0f;
#pragma unroll
            for (int w = 0; w < 6; w++) tot += s.red[w];
            out[0] = tot / (float)NBLK + seg[0];
            g_count = 0;
        }
    }
}

extern "C" void kernel_launch(void* const* d_in, const int* in_sizes, int n_in,
                              void* d_out, int out_size)
{
    const float* pred = (const float*)d_in[0];
    const float* tgt  = (const float*)d_in[1];
    const float* seg  = (const float*)d_in[2];
    float* out = (float*)d_out;

    static int attr_set = 0;
    const int smem = (int)sizeof(SMLayout);
    if (!attr_set){
        cudaFuncSetAttribute(clr_main, cudaFuncAttributeMaxDynamicSharedMemorySize, smem);
        attr_set = 1;
    }
    clr_main<<<NBLK, NT, smem>>>(pred, tgt, seg, out);
}

// round 7
// speedup vs baseline: 3.0262x; 1.0054x over previous
#include <cuda_runtime.h>
#include <math.h>

#define NPTS     72
#define NSTRIPSF 71.0f
#define NLANE    4
#define NP       192
#define BATCH    512
#define DD       78
#define NBLK     1536
#define IMGW     800.0f
#define IMGH     320.0f
#define XPITCH   74
#define SPITCH   7
#define NT       576

__device__ float    g_partials[NBLK];
__device__ unsigned g_count = 0;

__device__ __forceinline__ unsigned umn(unsigned a, unsigned b){ return a < b ? a : b; }
__device__ __forceinline__ unsigned umx(unsigned a, unsigned b){ return a > b ? a : b; }
__device__ __forceinline__ unsigned fkey(float f){
    int b = __float_as_int(f);
    return (b >= 0) ? ((unsigned)b ^ 0x80000000u) : ~((unsigned)b);
}
__device__ __forceinline__ float smooth_l1(float x){
    float a = fabsf(x);
    return (a < 1.0f) ? 0.5f * x * x : a - 0.5f;
}
// partial barrier over threads 0..191 (warps 0-5)
__device__ __forceinline__ void barL(){
    asm volatile("bar.sync 1, 192;" ::: "memory");
}

struct __align__(16) SMLayout {
    float    xs[NP * XPITCH];     // pred xs premultiplied by 799 (pitch 74: LDS.64 conflict-free)
    float    scal[NP * SPITCH];   // p0..p5
    float    tx[NLANE * NPTS];    // raw target xs per lane
    unsigned key[NLANE * NP];     // PHASE A: scratch plane 1 (third-1 partials); PHASE B: cost keys
    float    iouc[NLANE * NP];    // PHASE A: scratch plane 2 (third-2 partials); PHASE B: raw iou
    float    laneA[NLANE * 8];    // [0]=valid [1]=nv [2..5]=t2..5 [6]=30*nv
    int      startL[NLANE], endL[NLANE];
    unsigned k4[NLANE][4];
    int      dks[NLANE];
    unsigned thr[NLANE];
    float    red[32];
    int      lastFlag;
};

__global__ void __launch_bounds__(NT, 3)
clr_main(const float* __restrict__ predA, const float* __restrict__ tgtA,
         const float* __restrict__ seg, float* __restrict__ out)
{
    extern __shared__ char smraw[];
    SMLayout& s = *reinterpret_cast<SMLayout*>(smraw);

    const int tid  = threadIdx.x;
    const int wid  = tid >> 5;
    const int lane = tid & 31;
    const int g    = tid / NP;           // third index 0,1,2
    const int p    = tid - g * NP;       // prior index
    const int blk  = blockIdx.x;
    const int b    = blk & (BATCH - 1);

    const float2* pred2 = (const float2*)(predA + (size_t)blk * (NP * DD));
    const float*  tgt   = tgtA + (size_t)b * (NLANE * DD);

    // ---- stage predictions (coalesced float2; 13*576 = 7488 exact) ----
#pragma unroll
    for (int k = 0; k < 13; k++){
        int idx = tid + k * NT;
        int r = idx / 39, c2 = idx - r * 39;
        float2 v = pred2[idx];
        if (c2 < 3){
            s.scal[r * SPITCH + 2 * c2]     = v.x;
            s.scal[r * SPITCH + 2 * c2 + 1] = v.y;
        } else {
            int c = 2 * c2 - 6;
            s.xs[r * XPITCH + c]     = v.x * (IMGW - 1.0f);
            s.xs[r * XPITCH + c + 1] = v.y * (IMGW - 1.0f);
        }
    }

    // ---- stage targets, find contiguous valid run per lane (warps 0..3) ----
    if (wid < NLANE){
        const float* t = tgt + wid * DD;
        unsigned m[3];
#pragma unroll
        for (int c = 0; c < 3; c++){
            int j = c * 32 + lane;
            float x = (j < NPTS) ? t[6 + j] : -1.0f;
            if (j < NPTS) s.tx[wid * NPTS + j] = x;
            m[c] = __ballot_sync(0xffffffffu, (x >= 0.0f) && (x < IMGW));
        }
        if (lane == 0){
            int nv = __popc(m[0]) + __popc(m[1]) + __popc(m[2]);
            int st = m[0] ? (__ffs(m[0]) - 1) : (m[1] ? (31 + __ffs(m[1])) : (m[2] ? (63 + __ffs(m[2])) : 0));
            int en = m[2] ? (96 - __clz(m[2])) : (m[1] ? (64 - __clz(m[1])) : (m[0] ? (32 - __clz(m[0])) : 0));
            s.startL[wid] = st; s.endL[wid] = en;
            float* la = s.laneA + wid * 8;
            la[0] = (t[1] == 1.0f) ? 1.0f : 0.0f;
            la[1] = (float)nv;
            la[2] = t[2]; la[3] = t[3]; la[4] = t[4]; la[5] = t[5];
            la[6] = 30.0f * (float)nv;
        }
    }
    __syncthreads();

    // ---- S third-loop: thread (p, g) sums its j-third via float2 ----
    const float* myxs = s.xs + p * XPITCH;
    float aS[NLANE];
#pragma unroll
    for (int l = 0; l < NLANE; l++){
        const int st0 = s.startL[l], en0 = s.endL[l];
        const int n   = en0 - st0;
        const int b1  = st0 + n / 3;
        const int b2  = st0 + (2 * n) / 3;
        const int lo  = (g == 0) ? st0 : (g == 1) ? b1 : b2;
        const int hi  = (g == 0) ? b1  : (g == 1) ? b2 : en0;
        const float* txl = s.tx + l * NPTS;
        float a0 = 0.0f, a1 = 0.0f;
        int j = lo;
        if ((j & 1) && j < hi){ a0 += fabsf(myxs[j] - txl[j]); j++; }
#pragma unroll 2
        for (; j + 1 < hi; j += 2){
            float2 a = *(const float2*)(myxs + j);
            float2 t = *(const float2*)(txl + j);
            a0 += fabsf(a.x - t.x);
            a1 += fabsf(a.y - t.y);
        }
        if (j < hi) a0 += fabsf(myxs[j] - txl[j]);
        aS[l] = a0 + a1;
    }
    {
        float* sc1 = (float*)s.key;
        float* sc2 = s.iouc;
        if (g == 1){
#pragma unroll
            for (int l = 0; l < NLANE; l++) sc1[l * NP + p] = aS[l];
        } else if (g == 2){
#pragma unroll
            for (int l = 0; l < NLANE; l++) sc2[l * NP + p] = aS[l];
        }
    }
    __syncthreads();
    if (tid >= NP) return;          // warps 6-17 done; warps 0-5 use named barriers only

    // ================= PHASE B: threads 0..191 =================
    const float* sc1 = (const float*)s.key;
    const float* sc2 = s.iouc;
    float myDist[NLANE];
#pragma unroll
    for (int l = 0; l < NLANE; l++){
        float S = (aS[l] + sc1[l * NP + tid]) + sc2[l * NP + tid];
        float nv30 = s.laneA[l * 8 + 6];
        float iou  = (nv30 - S) / (nv30 + S + 1e-9f);
        myDist[l]  = S / (s.laneA[l * 8 + 1] + 1e-9f);
        s.iouc[l * NP + tid] = iou;          // raw iou (same slot this thread read)
    }

    const float* ps = s.scal + tid * SPITCH;
    const float p2 = ps[2], p3 = ps[3], p4 = ps[4];
    const float py = p2 * (IMGH - 1.0f), pxc = p3 * (IMGW - 1.0f);

    // ---- max loop (sd/th computed inline, not kept) ----
    float lmD = -INFINITY, lmS = -INFINITY, lmT = -INFINITY;
    float num_t = 0.0f;
#pragma unroll
    for (int l = 0; l < NLANE; l++){
        const float* la = s.laneA + l * 8;
        float v = la[0];
        num_t += v;
        float dy = py - la[2] * (IMGH - 1.0f);
        float dx = pxc - la[3];
        float sd = sqrtf(dy * dy + dx * dx);
        float th = fabsf(p4 - la[4]) * 180.0f;
        if (v > 0.0f){
            lmD = fmaxf(lmD, myDist[l]);
            lmS = fmaxf(lmS, sd);
            lmT = fmaxf(lmT, th);
        }
    }
    const bool has_t = num_t > 0.0f;

#pragma unroll
    for (int o2 = 16; o2; o2 >>= 1){
        lmD = fmaxf(lmD, __shfl_xor_sync(0xffffffffu, lmD, o2));
        lmS = fmaxf(lmS, __shfl_xor_sync(0xffffffffu, lmS, o2));
        lmT = fmaxf(lmT, __shfl_xor_sync(0xffffffffu, lmT, o2));
    }
    if (lane == 0){ s.red[wid] = lmD; s.red[8 + wid] = lmS; s.red[16 + wid] = lmT; }
    barL();
    float mD = s.red[0], mS = s.red[8], mT = s.red[16];
#pragma unroll
    for (int w = 1; w < 6; w++){
        mD = fmaxf(mD, s.red[w]);
        mS = fmaxf(mS, s.red[8 + w]);
        mT = fmaxf(mT, s.red[16 + w]);
    }
    if (!has_t){ mD = 1.0f; mS = 1.0f; mT = 1.0f; }

    // ---- classification cost ----
    const float p1v = ps[1];
    float sp1  = 1.0f / (1.0f + expf(-p1v));
    float neg1 = -logf(1.0f - sp1 + 1e-12f) * 0.75f * sp1 * sp1;
    float pos1 = -logf(sp1 + 1e-12f) * 0.25f * (1.0f - sp1) * (1.0f - sp1);
    float clsc = pos1 - neg1;

    // ---- cost loop: recompute sd/th, emit keys; track amin via key ----
    unsigned bestk = 0xFFFFFFFFu; int amin = 0;
#pragma unroll
    for (int l = 0; l < NLANE; l++){
        const float* la = s.laneA + l * 8;
        float v = la[0];
        float dy = py - la[2] * (IMGH - 1.0f);
        float dx = pxc - la[3];
        float sd = sqrtf(dy * dy + dx * dx);
        float th = fabsf(p4 - la[4]) * 180.0f;
        float ds = 1.0f - myDist[l] / mD + 0.01f;
        float ss = 1.0f - sd / mS + 0.01f;
        float ts = 1.0f - th / mT + 0.01f;
        float prod = ds * ss * ts;
        float c = -(prod * prod) * 3.0f + clsc;
        c = (v > 0.0f) ? c : INFINITY;
        unsigned k = fkey(c);
        s.key[l * NP + tid] = k;
        if (k < bestk){ bestk = k; amin = l; }
    }
    barL();

    // ---- selection: warps 0-3 cost-key top4; warps 4-5 iou top4 -> dyn_k ----
    if (wid < NLANE){
        const unsigned* kcol = s.key + wid * NP;
        unsigned s0 = 0xFFFFFFFFu, s1 = 0xFFFFFFFFu, s2 = 0xFFFFFFFFu, s3 = 0xFFFFFFFFu;
#pragma unroll
        for (int c = 0; c < 6; c++){
            unsigned x = kcol[c * 32 + lane];
            unsigned y = umn(s3, x);
            s3 = umx(s2, y); y = umn(s2, y);
            s2 = umx(s1, y); y = umn(s1, y);
            s1 = umx(s0, y); s0 = umn(s0, y);
        }
#pragma unroll
        for (int off = 16; off; off >>= 1){
            unsigned b0 = __shfl_xor_sync(0xffffffffu, s0, off);
            unsigned b1 = __shfl_xor_sync(0xffffffffu, s1, off);
            unsigned b2 = __shfl_xor_sync(0xffffffffu, s2, off);
            unsigned b3 = __shfl_xor_sync(0xffffffffu, s3, off);
            unsigned z0 = umn(s0, b3), z1 = umn(s1, b2), z2 = umn(s2, b1), z3 = umn(s3, b0);
            unsigned a;
            a = umn(z0, z2); z2 = umx(z0, z2); z0 = a;
            a = umn(z1, z3); z3 = umx(z1, z3); z1 = a;
            a = umn(z0, z1); z1 = umx(z0, z1); z0 = a;
            a = umn(z2, z3); z3 = umx(z2, z3); z2 = a;
            s0 = z0; s1 = z1; s2 = z2; s3 = z3;
        }
        if (lane == 0){
            s.k4[wid][0] = s0; s.k4[wid][1] = s1; s.k4[wid][2] = s2; s.k4[wid][3] = s3;
        }
    } else {
#pragma unroll
        for (int q = 0; q < 2; q++){
            int l = (wid - 4) * 2 + q;
            const float* icol = s.iouc + l * NP;
            float t0 = 0.f, t1 = 0.f, t2 = 0.f, t3 = 0.f;
#pragma unroll
            for (int c = 0; c < 6; c++){
                float x = fmaxf(icol[c * 32 + lane], 0.0f);   // clamp raw iou
                float y = fmaxf(t3, x);
                t3 = fminf(t2, y); y = fmaxf(t2, y);
                t2 = fminf(t1, y); y = fmaxf(t1, y);
                t1 = fminf(t0, y); t0 = fmaxf(t0, y);
            }
#pragma unroll
            for (int off = 16; off; off >>= 1){
                float b0 = __shfl_xor_sync(0xffffffffu, t0, off);
                float b1 = __shfl_xor_sync(0xffffffffu, t1, off);
                float b2 = __shfl_xor_sync(0xffffffffu, t2, off);
                float b3 = __shfl_xor_sync(0xffffffffu, t3, off);
                float z0 = fmaxf(t0, b3), z1 = fmaxf(t1, b2), z2 = fmaxf(t2, b1), z3 = fmaxf(t3, b0);
                float a;
                a = fmaxf(z0, z2); z2 = fminf(z0, z2); z0 = a;
                a = fmaxf(z1, z3); z3 = fminf(z1, z3); z1 = a;
                a = fmaxf(z0, z1); z1 = fminf(z0, z1); z0 = a;
                a = fmaxf(z2, z3); z3 = fminf(z2, z3); z2 = a;
                t0 = z0; t1 = z1; t2 = z2; t3 = z3;
            }
            if (lane == 0){
                float sum = ((t0 + t1) + t2) + t3;
                int dk = (int)sum;
                if (dk < 1) dk = 1; if (dk > 4) dk = 4;
                s.dks[l] = dk;
            }
        }
    }
    barL();
    if (tid < NLANE) s.thr[tid] = s.k4[tid][s.dks[tid] - 1];
    barL();

    // ---- matching (bitmask) ----
    int mmask = 0; int nM = 0;
#pragma unroll
    for (int l = 0; l < NLANE; l++){
        float v = s.laneA[l * 8];
        unsigned k = s.key[l * NP + tid];
        if (v > 0.0f && k <= s.thr[l]){ mmask |= (1 << l); nM++; }
    }
    if (nM > 1){ mmask &= ~1; mmask |= (1 << amin); }
    float mfsum = (float)__popc(mmask);
    int clsT = (mmask != 0) ? 1 : 0;

    // ---- focal ----
    const float p0v = ps[0];
    float mxl = fmaxf(p0v, p1v);
    float e0 = expf(p0v - mxl), e1 = expf(p1v - mxl);
    float pt = ((clsT ? e1 : e0) / (e0 + e1)) + 1e-8f;
    float focal = -0.25f * (1.0f - pt) * (1.0f - pt) * logf(pt);

    // ---- reg + iou epilogue ----
    const float p5v = ps[5];
    float yv = p2 * NSTRIPSF, tv = p4 * 180.0f, lv = p5v * NSTRIPSF;
    float pstart = fminf(fmaxf(rintf(p2 * NSTRIPSF), 0.0f), NSTRIPSF);
    float regp = 0.0f, ioup = 0.0f;
#pragma unroll
    for (int l = 0; l < NLANE; l++){
        if (mmask & (1 << l)){
            const float* la = s.laneA + l * 8;
            float d1 = yv - la[2] * NSTRIPSF;
            float d2 = pxc - la[3];
            float d3 = tv - la[4] * 180.0f;
            float tstart = rintf(la[2] * NSTRIPSF);
            float tlp = la[5] - (pstart - tstart);
            float d4 = lv - tlp;
            regp += smooth_l1(d1) + smooth_l1(d2) + smooth_l1(d3) + smooth_l1(d4);
            ioup += 1.0f - s.iouc[l * NP + tid];
        }
    }

    // ---- fused 4-way block sum over 192 threads ----
    float v0 = mfsum, v1 = focal, v2 = regp, v3 = ioup;
#pragma unroll
    for (int o2 = 16; o2; o2 >>= 1){
        v0 += __shfl_xor_sync(0xffffffffu, v0, o2);
        v1 += __shfl_xor_sync(0xffffffffu, v1, o2);
        v2 += __shfl_xor_sync(0xffffffffu, v2, o2);
        v3 += __shfl_xor_sync(0xffffffffu, v3, o2);
    }
    barL();
    if (lane == 0){ s.red[wid] = v0; s.red[8 + wid] = v1; s.red[16 + wid] = v2; s.red[24 + wid] = v3; }
    barL();
    if (tid == 0){
        float nmatch = 0.f, focal_s = 0.f, reg_s = 0.f, iou_s = 0.f;
#pragma unroll
        for (int w = 0; w < 6; w++){
            nmatch  += s.red[w];
            focal_s += s.red[8 + w];
            reg_s   += s.red[16 + w];
            iou_s   += s.red[24 + w];
        }
        float cls_term = focal_s / (has_t ? num_t : 1.0f);
        float reg_term = has_t ? reg_s / fmaxf(nmatch * 4.0f, 1.0f) : 0.0f;
        float iou_term = has_t ? iou_s / fmaxf(nmatch, 1.0f) : 0.0f;
        g_partials[blk] = 2.0f * cls_term + 0.2f * reg_term + 2.0f * iou_term;

        __threadfence();
        unsigned prev = atomicAdd(&g_count, 1u);
        s.lastFlag = (prev == NBLK - 1) ? 1 : 0;
    }
    barL();

    // ---- last block: deterministic final reduction ----
    if (s.lastFlag){
        __threadfence();
        float acc = 0.0f;
#pragma unroll
        for (int k = 0; k < 8; k++)
            acc += g_partials[tid + k * 192];
#pragma unroll
        for (int o2 = 16; o2; o2 >>= 1)
            acc += __shfl_xor_sync(0xffffffffu, acc, o2);
        barL();
        if (lane == 0) s.red[wid] = acc;
        barL();
        if (tid == 0){
            float tot = 0.0f;
#pragma unroll
            for (int w = 0; w < 6; w++) tot += s.red[w];
            out[0] = tot / (float)NBLK + seg[0];
            g_count = 0;
        }
    }
}

extern "C" void kernel_launch(void* const* d_in, const int* in_sizes, int n_in,
                              void* d_out, int out_size)
{
    const float* pred = (const float*)d_in[0];
    const float* tgt  = (const float*)d_in[1];
    const float* seg  = (const float*)d_in[2];
    float* out = (float*)d_out;

    static int attr_set = 0;
    const int smem = (int)sizeof(SMLayout);
    if (!attr_set){
        cudaFuncSetAttribute(clr_main, cudaFuncAttributeMaxDynamicSharedMemorySize, smem);
        attr_set = 1;
    }
    clr_main<<<NBLK, NT, smem>>>(pred, tgt, seg, out);
}